// round 13
// baseline (speedup 1.0000x reference)
#include <cuda_runtime.h>
#include <cuda_fp16.h>
#include <cstdint>

// ---------------------------------------------------------------------------
// SpatialPolicyHead: B=256, S=128 (rows 3..66 + row 0), H=1024, D=256, V=1858
//   fp = sq_hidden @ Wf^T + bf          (B*64, 256)
//   tp = sq_hidden @ Wt^T + bt          (B*64, 256)
//   gp = hidden[:,0,:] @ Wg^T + bg      (B, 256)
//   out[b,v] = sum_d relu(fp[b,f(v),d]*tp[b,t(v),d] + gp[b,d] + promo[p(v),d])*Ws[d] + bs
//
// R13: GEMM k-tile 128 (8 sync windows, 2-stage, 204KB smem); conv uses 16B
// stores and absorbs the gp kernel (blocks 4224..4287). Combine = R12.
// ---------------------------------------------------------------------------

// scratch (static device globals -- allocation-free)
__device__ __half g_Ah[16384 * 1024];   // gathered sq_hidden rows, fp16
__device__ __half g_Bh[512 * 1024];     // Wf (0..255) ++ Wt (256..511), fp16
__device__ __half g_fph[16384 * 256];   // fp results, fp16
__device__ __half g_tph[16384 * 256];   // tp results, fp16
__device__ float  g_gp [256 * 256];     // [B][256] fp32

// ---------------------------------------------------------------------------
// Pre-pass: gather + fp16-convert A (blocks 0..4095); convert B (4096..4223);
// gp GEMM (blocks 4224..4287, 4 batches each). 16B stores for A/B.
// ---------------------------------------------------------------------------
__global__ void __launch_bounds__(256) conv_kernel(
    const float* __restrict__ hidden,
    const float* __restrict__ Wf, const float* __restrict__ Wt,
    const float* __restrict__ Wg, const float* __restrict__ bg)
{
    const int tid = threadIdx.x;
    if (blockIdx.x < 4096) {
        const size_t base = (size_t)blockIdx.x * 1024;   // float4 index base
        #pragma unroll
        for (int j = 0; j < 2; j++) {
            const size_t i = base + (size_t)(tid + j * 256) * 2;  // even float4 idx
            const int m  = (int)(i >> 8);
            const int c4 = (int)(i & 255);
            const int row = (m >> 6) * 128 + 3 + (m & 63);
            const float4* src = (const float4*)(hidden + (size_t)row * 1024);
            const float4 v0 = src[c4];
            const float4 v1 = src[c4 + 1];
            uint4 o;
            ((__half2*)&o)[0] = __floats2half2_rn(v0.x, v0.y);
            ((__half2*)&o)[1] = __floats2half2_rn(v0.z, v0.w);
            ((__half2*)&o)[2] = __floats2half2_rn(v1.x, v1.y);
            ((__half2*)&o)[3] = __floats2half2_rn(v1.z, v1.w);
            ((uint4*)g_Ah)[i >> 1] = o;
        }
    } else if (blockIdx.x < 4224) {
        const size_t base = (size_t)(blockIdx.x - 4096) * 1024;
        #pragma unroll
        for (int j = 0; j < 2; j++) {
            const size_t i = base + (size_t)(tid + j * 256) * 2;
            const int n  = (int)(i >> 8);
            const int c4 = (int)(i & 255);
            const float* srcp = (n < 256) ? (Wf + (size_t)n * 1024)
                                          : (Wt + (size_t)(n - 256) * 1024);
            const float4* src = (const float4*)srcp;
            const float4 v0 = src[c4];
            const float4 v1 = src[c4 + 1];
            uint4 o;
            ((__half2*)&o)[0] = __floats2half2_rn(v0.x, v0.y);
            ((__half2*)&o)[1] = __floats2half2_rn(v0.z, v0.w);
            ((__half2*)&o)[2] = __floats2half2_rn(v1.x, v1.y);
            ((__half2*)&o)[3] = __floats2half2_rn(v1.z, v1.w);
            ((uint4*)g_Bh)[i >> 1] = o;
        }
    } else {
        // gp: 4 batches per block
        __shared__ float sh[4][1024];
        const int b0 = (blockIdx.x - 4224) * 4;
        #pragma unroll
        for (int i = 0; i < 4; i++) {
            const int idx = tid + i * 256;
            const int row = idx >> 8;
            const int col = idx & 255;
            ((float4*)&sh[row][0])[col] =
                ((const float4*)(hidden + (size_t)(b0 + row) * 131072))[col];
        }
        __syncthreads();

        const int n = tid;
        const float4* w4 = (const float4*)(Wg + (size_t)n * 1024);
        float acc0 = 0.f, acc1 = 0.f, acc2 = 0.f, acc3 = 0.f;
        #pragma unroll 4
        for (int k4 = 0; k4 < 256; k4++) {
            const float4 w  = w4[k4];
            const float4 h0 = ((const float4*)&sh[0][0])[k4];
            const float4 h1 = ((const float4*)&sh[1][0])[k4];
            const float4 h2 = ((const float4*)&sh[2][0])[k4];
            const float4 h3 = ((const float4*)&sh[3][0])[k4];
            acc0 = fmaf(w.x, h0.x, acc0); acc0 = fmaf(w.y, h0.y, acc0);
            acc0 = fmaf(w.z, h0.z, acc0); acc0 = fmaf(w.w, h0.w, acc0);
            acc1 = fmaf(w.x, h1.x, acc1); acc1 = fmaf(w.y, h1.y, acc1);
            acc1 = fmaf(w.z, h1.z, acc1); acc1 = fmaf(w.w, h1.w, acc1);
            acc2 = fmaf(w.x, h2.x, acc2); acc2 = fmaf(w.y, h2.y, acc2);
            acc2 = fmaf(w.z, h2.z, acc2); acc2 = fmaf(w.w, h2.w, acc2);
            acc3 = fmaf(w.x, h3.x, acc3); acc3 = fmaf(w.y, h3.y, acc3);
            acc3 = fmaf(w.z, h3.z, acc3); acc3 = fmaf(w.w, h3.w, acc3);
        }
        const float bias = bg[n];
        g_gp[(size_t)(b0 + 0) * 256 + n] = acc0 + bias;
        g_gp[(size_t)(b0 + 1) * 256 + n] = acc1 + bias;
        g_gp[(size_t)(b0 + 2) * 256 + n] = acc2 + bias;
        g_gp[(size_t)(b0 + 3) * 256 + n] = acc3 + bias;
    }
}

// ---------------------------------------------------------------------------
// fp16 tensor-core GEMM: grid (2,128): x=0 -> fp, 1 -> tp.
// 128(m) x 256(n) x 128(k) block tile, 512 threads = 16 warps (4m x 4n),
// warp tile 32x64. mma.sync.m16n8k16 f16->f32, 2-stage cp.async pipeline.
// smem/stage: A 128x136h (34816 B) + B 256x136h (69632 B) = 104448 B.
// Total 208896 B (< 227 KB limit).
// ---------------------------------------------------------------------------
#define KT 8                     // 1024/128 k-tiles
#define AST 136                  // halves per smem row (272 B)
#define ABUFH (128 * AST)
#define BBUFH (256 * AST)
#define GEMM_SMEM (2 * (ABUFH + BBUFH) * 2)   // 208896 B

__device__ __forceinline__ void mma_f16(float* c, const uint32_t* a, const uint32_t* b) {
    asm volatile(
        "mma.sync.aligned.m16n8k16.row.col.f32.f16.f16.f32 "
        "{%0,%1,%2,%3}, {%4,%5,%6,%7}, {%8,%9}, {%0,%1,%2,%3};"
        : "+f"(c[0]), "+f"(c[1]), "+f"(c[2]), "+f"(c[3])
        : "r"(a[0]), "r"(a[1]), "r"(a[2]), "r"(a[3]), "r"(b[0]), "r"(b[1]));
}

__global__ void __launch_bounds__(512) gemm_fpt_kernel(
    const float* __restrict__ bf, const float* __restrict__ bt)
{
    extern __shared__ __half hsm[];
    uint32_t sbase;
    asm("{ .reg .u64 t; cvta.to.shared.u64 t, %1; cvt.u32.u64 %0, t; }"
        : "=r"(sbase) : "l"(hsm));

    const int tid  = threadIdx.x;
    const int bn   = blockIdx.x;    // 0 = fp, 1 = tp
    const int bm   = blockIdx.y;
    const int warp = tid >> 5;
    const int lane = tid & 31;
    const int warp_m = warp >> 2;   // 0..3
    const int warp_n = warp & 3;    // 0..3
    const int lr = lane >> 2;       // 0..7
    const int lc = lane & 3;        // 0..3

    const __half* gAbase = g_Ah + (size_t)(bm * 128) * 1024;
    const __half* gBbase = g_Bh + (size_t)bn * 256 * 1024;

    float acc[2][8][4];
    #pragma unroll
    for (int i = 0; i < 2; i++)
        #pragma unroll
        for (int j = 0; j < 8; j++)
            #pragma unroll
            for (int k = 0; k < 4; k++) acc[i][j][k] = 0.f;

    // A: 128 rows x 16 chunks (16B each) = 2048 -> 4/thread
    // B: 256 rows x 16 chunks = 4096 -> 8/thread
    auto load_tile = [&](int t, int stg) {
        const uint32_t aB = sbase + (uint32_t)stg * (ABUFH + BBUFH) * 2;
        const uint32_t bB = aB + ABUFH * 2;
        #pragma unroll
        for (int j = 0; j < 4; j++) {
            const int id  = tid + 512 * j;
            const int row = id >> 4;
            const int cc  = id & 15;
            asm volatile("cp.async.ca.shared.global [%0], [%1], 16;" ::
                "r"(aB + (uint32_t)(row * (AST * 2) + cc * 16)),
                "l"(gAbase + (size_t)row * 1024 + t * 128 + cc * 8));
        }
        #pragma unroll
        for (int j = 0; j < 8; j++) {
            const int id  = tid + 512 * j;
            const int row = id >> 4;
            const int cc  = id & 15;
            asm volatile("cp.async.ca.shared.global [%0], [%1], 16;" ::
                "r"(bB + (uint32_t)(row * (AST * 2) + cc * 16)),
                "l"(gBbase + (size_t)row * 1024 + t * 128 + cc * 8));
        }
        asm volatile("cp.async.commit_group;" ::: "memory");
    };

    load_tile(0, 0);

    int stg = 0;
    for (int t = 0; t < KT; t++) {
        asm volatile("cp.async.wait_group 0;" ::: "memory");
        __syncthreads();

        if (t + 1 < KT)
            load_tile(t + 1, stg ^ 1);

        const __half* Ab = hsm + (size_t)stg * (ABUFH + BBUFH);
        const __half* Bb = Ab + ABUFH;
        #pragma unroll
        for (int ks = 0; ks < 8; ks++) {
            uint32_t afr[2][4], bfr[8][2];
            #pragma unroll
            for (int mt = 0; mt < 2; mt++) {
                const __half* p = Ab + (warp_m * 32 + mt * 16 + lr) * AST + ks * 16 + 2 * lc;
                afr[mt][0] = *(const uint32_t*)(p);
                afr[mt][1] = *(const uint32_t*)(p + 8 * AST);
                afr[mt][2] = *(const uint32_t*)(p + 8);
                afr[mt][3] = *(const uint32_t*)(p + 8 * AST + 8);
            }
            #pragma unroll
            for (int nt = 0; nt < 8; nt++) {
                const __half* q = Bb + (warp_n * 64 + nt * 8 + lr) * AST + ks * 16 + 2 * lc;
                bfr[nt][0] = *(const uint32_t*)(q);
                bfr[nt][1] = *(const uint32_t*)(q + 8);
            }
            #pragma unroll
            for (int mt = 0; mt < 2; mt++)
                #pragma unroll
                for (int nt = 0; nt < 8; nt++)
                    mma_f16(acc[mt][nt], afr[mt], bfr[nt]);
        }
        stg ^= 1;
    }

    // epilogue: bias add in fp32, store fp16 half2
    const float* bia_base = bn ? bt : bf;
    __half* outp = bn ? g_tph : g_fph;
    #pragma unroll
    for (int mt = 0; mt < 2; mt++) {
        const int gm0 = bm * 128 + warp_m * 32 + mt * 16 + lr;
        #pragma unroll
        for (int nt = 0; nt < 8; nt++) {
            const int n_loc = warp_n * 64 + nt * 8 + (lc << 1);   // 0..255
            const float b0 = bia_base[n_loc], b1 = bia_base[n_loc + 1];
            *(__half2*)&outp[(size_t)gm0 * 256 + n_loc] =
                __floats2half2_rn(acc[mt][nt][0] + b0, acc[mt][nt][1] + b1);
            *(__half2*)&outp[(size_t)(gm0 + 8) * 256 + n_loc] =
                __floats2half2_rn(acc[mt][nt][2] + b0, acc[mt][nt][3] + b1);
        }
    }
}

// ---------------------------------------------------------------------------
// Combine (R10/R12 proven config): 256 blocks, 1024 threads.
// smem (fp16): fp 64x256 + tp 64x256 + gpp 5x256 = 68096 B, where
// gpp[p][d] = gp[b][d] + promo[p][d]. 2 v per warp iter; 6-shfl dual reduce.
// ---------------------------------------------------------------------------
__global__ void __launch_bounds__(1024) combine_kernel(
    const float* __restrict__ promo_tab, const float* __restrict__ Ws,
    const float* __restrict__ bs,
    const int* __restrict__ from_sqs, const int* __restrict__ to_sqs,
    const int* __restrict__ promo_types,
    float* __restrict__ out)
{
    extern __shared__ __half hsm2[];
    __half* fp_s  = hsm2;            // 16384 halves
    __half* tp_s  = hsm2 + 16384;    // 16384 halves
    __half* gpp_s = hsm2 + 32768;    // 1280 halves

    const int tid = threadIdx.x;
    const int b   = blockIdx.x;

    {
        const uint4* sf = (const uint4*)(g_fph + (size_t)b * 16384);
        const uint4* st = (const uint4*)(g_tph + (size_t)b * 16384);
        uint4* df = (uint4*)fp_s;
        uint4* dt = (uint4*)tp_s;
        df[tid] = sf[tid]; df[tid + 1024] = sf[tid + 1024];
        dt[tid] = st[tid]; dt[tid + 1024] = st[tid + 1024];
        if (tid < 640) {
            const int p  = tid >> 7;
            const int d2 = tid & 127;
            const float2 pv = ((const float2*)(promo_tab + p * 256))[d2];
            const float2 gv = ((const float2*)(g_gp + (size_t)b * 256))[d2];
            ((__half2*)gpp_s)[tid] = __floats2half2_rn(pv.x + gv.x, pv.y + gv.y);
        }
    }

    const int lane = tid & 31;
    const int warp = tid >> 5;

    const float4 wsa = *(const float4*)(Ws + lane * 8);
    const float4 wsb = *(const float4*)(Ws + lane * 8 + 4);
    const float wsr[8] = { wsa.x, wsa.y, wsa.z, wsa.w, wsb.x, wsb.y, wsb.z, wsb.w };
    const float bs0 = __ldg(bs);
    const __half2 hzero = __float2half2_rn(0.f);

    __syncthreads();

    for (int v0 = warp * 2; v0 < 1858; v0 += 64) {
        const int v1 = v0 + 1;
        const int f0 = __ldg(from_sqs + v0),    f1 = __ldg(from_sqs + v1);
        const int t0 = __ldg(to_sqs + v0),      t1 = __ldg(to_sqs + v1);
        const int p0 = __ldg(promo_types + v0), p1 = __ldg(promo_types + v1);

        const uint4 fh0 = *(const uint4*)(fp_s  + f0 * 256 + lane * 8);
        const uint4 th0 = *(const uint4*)(tp_s  + t0 * 256 + lane * 8);
        const uint4 gh0 = *(const uint4*)(gpp_s + p0 * 256 + lane * 8);
        const uint4 fh1 = *(const uint4*)(fp_s  + f1 * 256 + lane * 8);
        const uint4 th1 = *(const uint4*)(tp_s  + t1 * 256 + lane * 8);
        const uint4 gh1 = *(const uint4*)(gpp_s + p1 * 256 + lane * 8);

        const uint32_t* fw0 = (const uint32_t*)&fh0;
        const uint32_t* tw0 = (const uint32_t*)&th0;
        const uint32_t* gw0 = (const uint32_t*)&gh0;
        const uint32_t* fw1 = (const uint32_t*)&fh1;
        const uint32_t* tw1 = (const uint32_t*)&th1;
        const uint32_t* gw1 = (const uint32_t*)&gh1;

        float acc0 = 0.f, acc1 = 0.f;
        #pragma unroll
        for (int j = 0; j < 4; j++) {
            __half2 c0 = __hfma2(*(const __half2*)&fw0[j], *(const __half2*)&tw0[j],
                                 *(const __half2*)&gw0[j]);
            __half2 c1 = __hfma2(*(const __half2*)&fw1[j], *(const __half2*)&tw1[j],
                                 *(const __half2*)&gw1[j]);
            c0 = __hmax2(c0, hzero);
            c1 = __hmax2(c1, hzero);
            const float2 r0 = __half22float2(c0);
            const float2 r1 = __half22float2(c1);
            acc0 = fmaf(r0.x, wsr[2*j],     acc0);
            acc0 = fmaf(r0.y, wsr[2*j + 1], acc0);
            acc1 = fmaf(r1.x, wsr[2*j],     acc1);
            acc1 = fmaf(r1.y, wsr[2*j + 1], acc1);
        }

        // dual reduction: fold lane^16 for each chain, select halves, 4 levels
        const float a = acc0 + __shfl_xor_sync(0xffffffffu, acc0, 16);
        const float c = acc1 + __shfl_xor_sync(0xffffffffu, acc1, 16);
        float r = (lane & 16) ? c : a;
        r += __shfl_xor_sync(0xffffffffu, r, 8);
        r += __shfl_xor_sync(0xffffffffu, r, 4);
        r += __shfl_xor_sync(0xffffffffu, r, 2);
        r += __shfl_xor_sync(0xffffffffu, r, 1);
        if (lane == 0)  out[(size_t)b * 1858 + v0] = r + bs0;
        if (lane == 16) out[(size_t)b * 1858 + v1] = r + bs0;
    }
}

// ---------------------------------------------------------------------------
extern "C" void kernel_launch(void* const* d_in, const int* in_sizes, int n_in,
                              void* d_out, int out_size)
{
    (void)in_sizes; (void)n_in; (void)out_size;

    const float* hidden      = (const float*)d_in[0];
    const float* Wf          = (const float*)d_in[1];
    const float* bf          = (const float*)d_in[2];
    const float* Wt          = (const float*)d_in[3];
    const float* bt          = (const float*)d_in[4];
    const float* Wg          = (const float*)d_in[5];
    const float* bg          = (const float*)d_in[6];
    const float* promo_tab   = (const float*)d_in[7];
    const float* Ws          = (const float*)d_in[8];
    const float* bs          = (const float*)d_in[9];
    const int*   from_sqs    = (const int*)d_in[10];
    const int*   to_sqs      = (const int*)d_in[11];
    const int*   promo_types = (const int*)d_in[12];
    float*       out         = (float*)d_out;

    // 1) gather + fp16 convert pre-pass (A, B) + gp fused
    conv_kernel<<<4288, 256>>>(hidden, Wf, Wt, Wg, bg);

    // 2) fp16 tensor-core fp/tp GEMM (128x256x128, 16 warps, 2-stage)
    cudaFuncSetAttribute(gemm_fpt_kernel,
                         cudaFuncAttributeMaxDynamicSharedMemorySize, GEMM_SMEM);
    gemm_fpt_kernel<<<dim3(2, 128), 512, GEMM_SMEM>>>(bf, bt);

    // 3) combine (proven config)
    const int comb_smem = (16384 + 16384 + 1280) * 2;   // 68096 B
    cudaFuncSetAttribute(combine_kernel,
                         cudaFuncAttributeMaxDynamicSharedMemorySize, comb_smem);
    combine_kernel<<<256, 1024, comb_smem>>>(promo_tab, Ws, bs,
                                             from_sqs, to_sqs, promo_types, out);
}

// round 14
// speedup vs baseline: 1.1899x; 1.1899x over previous
#include <cuda_runtime.h>
#include <cuda_fp16.h>
#include <cstdint>

// ---------------------------------------------------------------------------
// SpatialPolicyHead: B=256, S=128 (rows 3..66 + row 0), H=1024, D=256, V=1858
//   fp = sq_hidden @ Wf^T + bf          (B*64, 256)
//   tp = sq_hidden @ Wt^T + bt          (B*64, 256)
//   gp = hidden[:,0,:] @ Wg^T + bg      (B, 256)
//   out[b,v] = sum_d relu(fp[b,f(v),d]*tp[b,t(v),d] + gp[b,d] + promo[p(v),d])*Ws[d] + bs
//
// R14: conv reverted to coalesced loads (batched MLP-4, single STG.64 per
// float4); gp separate again; GEMM keeps R13's k128 (measured ~27us);
// combine = R12.
// ---------------------------------------------------------------------------

// scratch (static device globals -- allocation-free)
__device__ __half g_Ah[16384 * 1024];   // gathered sq_hidden rows, fp16
__device__ __half g_Bh[512 * 1024];     // Wf (0..255) ++ Wt (256..511), fp16
__device__ __half g_fph[16384 * 256];   // fp results, fp16
__device__ __half g_tph[16384 * 256];   // tp results, fp16
__device__ float  g_gp [256 * 256];     // [B][256] fp32

// ---------------------------------------------------------------------------
// Pre-pass: gather + fp16-convert A (blocks 0..4095); convert B (4096..4223).
// Coalesced: thread handles float4 indices base + tid + j*256 (consecutive
// across lanes). Loads batched first (MLP 4), then 8B stores.
// ---------------------------------------------------------------------------
__global__ void __launch_bounds__(256) conv_kernel(
    const float* __restrict__ hidden,
    const float* __restrict__ Wf, const float* __restrict__ Wt)
{
    const int tid = threadIdx.x;
    if (blockIdx.x < 4096) {
        const size_t base = (size_t)blockIdx.x * 1024;
        float4 v[4];
        size_t idx[4];
        #pragma unroll
        for (int j = 0; j < 4; j++) {
            const size_t i = base + tid + j * 256;   // float4 index
            idx[j] = i;
            const int m  = (int)(i >> 8);
            const int c4 = (int)(i & 255);
            const int row = (m >> 6) * 128 + 3 + (m & 63);
            v[j] = ((const float4*)(hidden + (size_t)row * 1024))[c4];
        }
        #pragma unroll
        for (int j = 0; j < 4; j++) {
            uint2 o;
            ((__half2*)&o)[0] = __floats2half2_rn(v[j].x, v[j].y);
            ((__half2*)&o)[1] = __floats2half2_rn(v[j].z, v[j].w);
            ((uint2*)g_Ah)[idx[j]] = o;
        }
    } else {
        const size_t base = (size_t)(blockIdx.x - 4096) * 1024;
        float4 v[4];
        size_t idx[4];
        #pragma unroll
        for (int j = 0; j < 4; j++) {
            const size_t i = base + tid + j * 256;
            idx[j] = i;
            const int n  = (int)(i >> 8);
            const int c4 = (int)(i & 255);
            const float* src = (n < 256) ? (Wf + (size_t)n * 1024)
                                         : (Wt + (size_t)(n - 256) * 1024);
            v[j] = ((const float4*)src)[c4];
        }
        #pragma unroll
        for (int j = 0; j < 4; j++) {
            uint2 o;
            ((__half2*)&o)[0] = __floats2half2_rn(v[j].x, v[j].y);
            ((__half2*)&o)[1] = __floats2half2_rn(v[j].z, v[j].w);
            ((uint2*)g_Bh)[idx[j]] = o;
        }
    }
}

// ---------------------------------------------------------------------------
// fp16 tensor-core GEMM: grid (2,128): x=0 -> fp, 1 -> tp.
// 128(m) x 256(n) x 128(k) block tile, 512 threads = 16 warps (4m x 4n),
// warp tile 32x64. mma.sync.m16n8k16 f16->f32, 2-stage cp.async pipeline.
// smem/stage: A 128x136h (34816 B) + B 256x136h (69632 B) = 104448 B.
// Total 208896 B.
// ---------------------------------------------------------------------------
#define KT 8                     // 1024/128 k-tiles
#define AST 136                  // halves per smem row (272 B)
#define ABUFH (128 * AST)
#define BBUFH (256 * AST)
#define GEMM_SMEM (2 * (ABUFH + BBUFH) * 2)   // 208896 B

__device__ __forceinline__ void mma_f16(float* c, const uint32_t* a, const uint32_t* b) {
    asm volatile(
        "mma.sync.aligned.m16n8k16.row.col.f32.f16.f16.f32 "
        "{%0,%1,%2,%3}, {%4,%5,%6,%7}, {%8,%9}, {%0,%1,%2,%3};"
        : "+f"(c[0]), "+f"(c[1]), "+f"(c[2]), "+f"(c[3])
        : "r"(a[0]), "r"(a[1]), "r"(a[2]), "r"(a[3]), "r"(b[0]), "r"(b[1]));
}

__global__ void __launch_bounds__(512) gemm_fpt_kernel(
    const float* __restrict__ bf, const float* __restrict__ bt)
{
    extern __shared__ __half hsm[];
    uint32_t sbase;
    asm("{ .reg .u64 t; cvta.to.shared.u64 t, %1; cvt.u32.u64 %0, t; }"
        : "=r"(sbase) : "l"(hsm));

    const int tid  = threadIdx.x;
    const int bn   = blockIdx.x;    // 0 = fp, 1 = tp
    const int bm   = blockIdx.y;
    const int warp = tid >> 5;
    const int lane = tid & 31;
    const int warp_m = warp >> 2;   // 0..3
    const int warp_n = warp & 3;    // 0..3
    const int lr = lane >> 2;       // 0..7
    const int lc = lane & 3;        // 0..3

    const __half* gAbase = g_Ah + (size_t)(bm * 128) * 1024;
    const __half* gBbase = g_Bh + (size_t)bn * 256 * 1024;

    float acc[2][8][4];
    #pragma unroll
    for (int i = 0; i < 2; i++)
        #pragma unroll
        for (int j = 0; j < 8; j++)
            #pragma unroll
            for (int k = 0; k < 4; k++) acc[i][j][k] = 0.f;

    // A: 128 rows x 16 chunks (16B each) = 2048 -> 4/thread
    // B: 256 rows x 16 chunks = 4096 -> 8/thread
    auto load_tile = [&](int t, int stg) {
        const uint32_t aB = sbase + (uint32_t)stg * (ABUFH + BBUFH) * 2;
        const uint32_t bB = aB + ABUFH * 2;
        #pragma unroll
        for (int j = 0; j < 4; j++) {
            const int id  = tid + 512 * j;
            const int row = id >> 4;
            const int cc  = id & 15;
            asm volatile("cp.async.ca.shared.global [%0], [%1], 16;" ::
                "r"(aB + (uint32_t)(row * (AST * 2) + cc * 16)),
                "l"(gAbase + (size_t)row * 1024 + t * 128 + cc * 8));
        }
        #pragma unroll
        for (int j = 0; j < 8; j++) {
            const int id  = tid + 512 * j;
            const int row = id >> 4;
            const int cc  = id & 15;
            asm volatile("cp.async.ca.shared.global [%0], [%1], 16;" ::
                "r"(bB + (uint32_t)(row * (AST * 2) + cc * 16)),
                "l"(gBbase + (size_t)row * 1024 + t * 128 + cc * 8));
        }
        asm volatile("cp.async.commit_group;" ::: "memory");
    };

    load_tile(0, 0);

    int stg = 0;
    for (int t = 0; t < KT; t++) {
        asm volatile("cp.async.wait_group 0;" ::: "memory");
        __syncthreads();

        if (t + 1 < KT)
            load_tile(t + 1, stg ^ 1);

        const __half* Ab = hsm + (size_t)stg * (ABUFH + BBUFH);
        const __half* Bb = Ab + ABUFH;
        #pragma unroll
        for (int ks = 0; ks < 8; ks++) {
            uint32_t afr[2][4], bfr[8][2];
            #pragma unroll
            for (int mt = 0; mt < 2; mt++) {
                const __half* p = Ab + (warp_m * 32 + mt * 16 + lr) * AST + ks * 16 + 2 * lc;
                afr[mt][0] = *(const uint32_t*)(p);
                afr[mt][1] = *(const uint32_t*)(p + 8 * AST);
                afr[mt][2] = *(const uint32_t*)(p + 8);
                afr[mt][3] = *(const uint32_t*)(p + 8 * AST + 8);
            }
            #pragma unroll
            for (int nt = 0; nt < 8; nt++) {
                const __half* q = Bb + (warp_n * 64 + nt * 8 + lr) * AST + ks * 16 + 2 * lc;
                bfr[nt][0] = *(const uint32_t*)(q);
                bfr[nt][1] = *(const uint32_t*)(q + 8);
            }
            #pragma unroll
            for (int mt = 0; mt < 2; mt++)
                #pragma unroll
                for (int nt = 0; nt < 8; nt++)
                    mma_f16(acc[mt][nt], afr[mt], bfr[nt]);
        }
        stg ^= 1;
    }

    // epilogue: bias add in fp32, store fp16 half2
    const float* bia_base = bn ? bt : bf;
    __half* outp = bn ? g_tph : g_fph;
    #pragma unroll
    for (int mt = 0; mt < 2; mt++) {
        const int gm0 = bm * 128 + warp_m * 32 + mt * 16 + lr;
        #pragma unroll
        for (int nt = 0; nt < 8; nt++) {
            const int n_loc = warp_n * 64 + nt * 8 + (lc << 1);   // 0..255
            const float b0 = bia_base[n_loc], b1 = bia_base[n_loc + 1];
            *(__half2*)&outp[(size_t)gm0 * 256 + n_loc] =
                __floats2half2_rn(acc[mt][nt][0] + b0, acc[mt][nt][1] + b1);
            *(__half2*)&outp[(size_t)(gm0 + 8) * 256 + n_loc] =
                __floats2half2_rn(acc[mt][nt][2] + b0, acc[mt][nt][3] + b1);
        }
    }
}

// ---------------------------------------------------------------------------
// gp GEMM (fp32, tiny): 64 blocks x 4 batches.
// ---------------------------------------------------------------------------
__global__ void __launch_bounds__(256) gp_kernel(
    const float* __restrict__ hidden,
    const float* __restrict__ Wg, const float* __restrict__ bg)
{
    __shared__ float sh[4][1024];
    const int tid = threadIdx.x;
    const int b0  = blockIdx.x * 4;

    #pragma unroll
    for (int i = 0; i < 4; i++) {
        const int idx = tid + i * 256;
        const int row = idx >> 8;
        const int col = idx & 255;
        ((float4*)&sh[row][0])[col] =
            ((const float4*)(hidden + (size_t)(b0 + row) * 131072))[col];
    }
    __syncthreads();

    const int n = tid;
    const float4* w4 = (const float4*)(Wg + (size_t)n * 1024);
    float acc0 = 0.f, acc1 = 0.f, acc2 = 0.f, acc3 = 0.f;
    #pragma unroll 4
    for (int k4 = 0; k4 < 256; k4++) {
        const float4 w  = w4[k4];
        const float4 h0 = ((const float4*)&sh[0][0])[k4];
        const float4 h1 = ((const float4*)&sh[1][0])[k4];
        const float4 h2 = ((const float4*)&sh[2][0])[k4];
        const float4 h3 = ((const float4*)&sh[3][0])[k4];
        acc0 = fmaf(w.x, h0.x, acc0); acc0 = fmaf(w.y, h0.y, acc0);
        acc0 = fmaf(w.z, h0.z, acc0); acc0 = fmaf(w.w, h0.w, acc0);
        acc1 = fmaf(w.x, h1.x, acc1); acc1 = fmaf(w.y, h1.y, acc1);
        acc1 = fmaf(w.z, h1.z, acc1); acc1 = fmaf(w.w, h1.w, acc1);
        acc2 = fmaf(w.x, h2.x, acc2); acc2 = fmaf(w.y, h2.y, acc2);
        acc2 = fmaf(w.z, h2.z, acc2); acc2 = fmaf(w.w, h2.w, acc2);
        acc3 = fmaf(w.x, h3.x, acc3); acc3 = fmaf(w.y, h3.y, acc3);
        acc3 = fmaf(w.z, h3.z, acc3); acc3 = fmaf(w.w, h3.w, acc3);
    }
    const float bias = bg[n];
    g_gp[(size_t)(b0 + 0) * 256 + n] = acc0 + bias;
    g_gp[(size_t)(b0 + 1) * 256 + n] = acc1 + bias;
    g_gp[(size_t)(b0 + 2) * 256 + n] = acc2 + bias;
    g_gp[(size_t)(b0 + 3) * 256 + n] = acc3 + bias;
}

// ---------------------------------------------------------------------------
// Combine (R12 proven config): 256 blocks, 1024 threads.
// smem (fp16): fp 64x256 + tp 64x256 + gpp 5x256 = 68096 B, where
// gpp[p][d] = gp[b][d] + promo[p][d]. 2 v per warp iter; 6-shfl dual reduce.
// ---------------------------------------------------------------------------
__global__ void __launch_bounds__(1024) combine_kernel(
    const float* __restrict__ promo_tab, const float* __restrict__ Ws,
    const float* __restrict__ bs,
    const int* __restrict__ from_sqs, const int* __restrict__ to_sqs,
    const int* __restrict__ promo_types,
    float* __restrict__ out)
{
    extern __shared__ __half hsm2[];
    __half* fp_s  = hsm2;            // 16384 halves
    __half* tp_s  = hsm2 + 16384;    // 16384 halves
    __half* gpp_s = hsm2 + 32768;    // 1280 halves

    const int tid = threadIdx.x;
    const int b   = blockIdx.x;

    {
        const uint4* sf = (const uint4*)(g_fph + (size_t)b * 16384);
        const uint4* st = (const uint4*)(g_tph + (size_t)b * 16384);
        uint4* df = (uint4*)fp_s;
        uint4* dt = (uint4*)tp_s;
        df[tid] = sf[tid]; df[tid + 1024] = sf[tid + 1024];
        dt[tid] = st[tid]; dt[tid + 1024] = st[tid + 1024];
        if (tid < 640) {
            const int p  = tid >> 7;
            const int d2 = tid & 127;
            const float2 pv = ((const float2*)(promo_tab + p * 256))[d2];
            const float2 gv = ((const float2*)(g_gp + (size_t)b * 256))[d2];
            ((__half2*)gpp_s)[tid] = __floats2half2_rn(pv.x + gv.x, pv.y + gv.y);
        }
    }

    const int lane = tid & 31;
    const int warp = tid >> 5;

    const float4 wsa = *(const float4*)(Ws + lane * 8);
    const float4 wsb = *(const float4*)(Ws + lane * 8 + 4);
    const float wsr[8] = { wsa.x, wsa.y, wsa.z, wsa.w, wsb.x, wsb.y, wsb.z, wsb.w };
    const float bs0 = __ldg(bs);
    const __half2 hzero = __float2half2_rn(0.f);

    __syncthreads();

    for (int v0 = warp * 2; v0 < 1858; v0 += 64) {
        const int v1 = v0 + 1;
        const int f0 = __ldg(from_sqs + v0),    f1 = __ldg(from_sqs + v1);
        const int t0 = __ldg(to_sqs + v0),      t1 = __ldg(to_sqs + v1);
        const int p0 = __ldg(promo_types + v0), p1 = __ldg(promo_types + v1);

        const uint4 fh0 = *(const uint4*)(fp_s  + f0 * 256 + lane * 8);
        const uint4 th0 = *(const uint4*)(tp_s  + t0 * 256 + lane * 8);
        const uint4 gh0 = *(const uint4*)(gpp_s + p0 * 256 + lane * 8);
        const uint4 fh1 = *(const uint4*)(fp_s  + f1 * 256 + lane * 8);
        const uint4 th1 = *(const uint4*)(tp_s  + t1 * 256 + lane * 8);
        const uint4 gh1 = *(const uint4*)(gpp_s + p1 * 256 + lane * 8);

        const uint32_t* fw0 = (const uint32_t*)&fh0;
        const uint32_t* tw0 = (const uint32_t*)&th0;
        const uint32_t* gw0 = (const uint32_t*)&gh0;
        const uint32_t* fw1 = (const uint32_t*)&fh1;
        const uint32_t* tw1 = (const uint32_t*)&th1;
        const uint32_t* gw1 = (const uint32_t*)&gh1;

        float acc0 = 0.f, acc1 = 0.f;
        #pragma unroll
        for (int j = 0; j < 4; j++) {
            __half2 c0 = __hfma2(*(const __half2*)&fw0[j], *(const __half2*)&tw0[j],
                                 *(const __half2*)&gw0[j]);
            __half2 c1 = __hfma2(*(const __half2*)&fw1[j], *(const __half2*)&tw1[j],
                                 *(const __half2*)&gw1[j]);
            c0 = __hmax2(c0, hzero);
            c1 = __hmax2(c1, hzero);
            const float2 r0 = __half22float2(c0);
            const float2 r1 = __half22float2(c1);
            acc0 = fmaf(r0.x, wsr[2*j],     acc0);
            acc0 = fmaf(r0.y, wsr[2*j + 1], acc0);
            acc1 = fmaf(r1.x, wsr[2*j],     acc1);
            acc1 = fmaf(r1.y, wsr[2*j + 1], acc1);
        }

        // dual reduction: fold lane^16 for each chain, select halves, 4 levels
        const float a = acc0 + __shfl_xor_sync(0xffffffffu, acc0, 16);
        const float c = acc1 + __shfl_xor_sync(0xffffffffu, acc1, 16);
        float r = (lane & 16) ? c : a;
        r += __shfl_xor_sync(0xffffffffu, r, 8);
        r += __shfl_xor_sync(0xffffffffu, r, 4);
        r += __shfl_xor_sync(0xffffffffu, r, 2);
        r += __shfl_xor_sync(0xffffffffu, r, 1);
        if (lane == 0)  out[(size_t)b * 1858 + v0] = r + bs0;
        if (lane == 16) out[(size_t)b * 1858 + v1] = r + bs0;
    }
}

// ---------------------------------------------------------------------------
extern "C" void kernel_launch(void* const* d_in, const int* in_sizes, int n_in,
                              void* d_out, int out_size)
{
    (void)in_sizes; (void)n_in; (void)out_size;

    const float* hidden      = (const float*)d_in[0];
    const float* Wf          = (const float*)d_in[1];
    const float* bf          = (const float*)d_in[2];
    const float* Wt          = (const float*)d_in[3];
    const float* bt          = (const float*)d_in[4];
    const float* Wg          = (const float*)d_in[5];
    const float* bg          = (const float*)d_in[6];
    const float* promo_tab   = (const float*)d_in[7];
    const float* Ws          = (const float*)d_in[8];
    const float* bs          = (const float*)d_in[9];
    const int*   from_sqs    = (const int*)d_in[10];
    const int*   to_sqs      = (const int*)d_in[11];
    const int*   promo_types = (const int*)d_in[12];
    float*       out         = (float*)d_out;

    // 1) gather + fp16 convert pre-pass (coalesced)
    conv_kernel<<<4224, 256>>>(hidden, Wf, Wt);

    // 2) fp16 tensor-core fp/tp GEMM (128x256x128, 16 warps, 2-stage)
    cudaFuncSetAttribute(gemm_fpt_kernel,
                         cudaFuncAttributeMaxDynamicSharedMemorySize, GEMM_SMEM);
    gemm_fpt_kernel<<<dim3(2, 128), 512, GEMM_SMEM>>>(bf, bt);

    // 3) gp
    gp_kernel<<<64, 256>>>(hidden, Wg, bg);

    // 4) combine (proven config)
    const int comb_smem = (16384 + 16384 + 1280) * 2;   // 68096 B
    cudaFuncSetAttribute(combine_kernel,
                         cudaFuncAttributeMaxDynamicSharedMemorySize, comb_smem);
    combine_kernel<<<256, 1024, comb_smem>>>(promo_tab, Ws, bs,
                                             from_sqs, to_sqs, promo_types, out);
}

// round 15
// speedup vs baseline: 1.2174x; 1.0232x over previous
#include <cuda_runtime.h>
#include <cuda_fp16.h>
#include <cstdint>

// ---------------------------------------------------------------------------
// SpatialPolicyHead: B=256, S=128 (rows 3..66 + row 0), H=1024, D=256, V=1858
//   fp = sq_hidden @ Wf^T + bf          (B*64, 256)
//   tp = sq_hidden @ Wt^T + bt          (B*64, 256)
//   gp = hidden[:,0,:] @ Wg^T + bg      (B, 256)
//   out[b,v] = sum_d relu(fp[b,f(v),d]*tp[b,t(v),d] + gp[b,d] + promo[p(v),d])*Ws[d] + bs
//
// R15: exact R12 base (gemm k64 2-CTA/SM, gp, combine) + conv rewritten for
// MLP=8 (512 threads, 8 batched LDG.128 per thread, uint2 stores).
// ---------------------------------------------------------------------------

// scratch (static device globals -- allocation-free)
__device__ __half g_Ah[16384 * 1024];   // gathered sq_hidden rows, fp16
__device__ __half g_Bh[512 * 1024];     // Wf (0..255) ++ Wt (256..511), fp16
__device__ __half g_fph[16384 * 256];   // fp results, fp16
__device__ __half g_tph[16384 * 256];   // tp results, fp16
__device__ float  g_gp [256 * 256];     // [B][256] fp32

// ---------------------------------------------------------------------------
// Pre-pass: gather + fp16-convert A (blocks 0..1023); convert B (1024..1055).
// 512 threads; each thread: 8 batched float4 loads (MLP 8), then 8 uint2 stores.
// Block covers 4096 consecutive float4 (A: 16 m-rows; B: 16 n-rows).
// ---------------------------------------------------------------------------
__global__ void __launch_bounds__(512) conv_kernel(
    const float* __restrict__ hidden,
    const float* __restrict__ Wf, const float* __restrict__ Wt)
{
    const int tid = threadIdx.x;
    float4 v[8];
    if (blockIdx.x < 1024) {
        const size_t base = (size_t)blockIdx.x * 4096;
        #pragma unroll
        for (int j = 0; j < 8; j++) {
            const size_t i = base + tid + j * 512;   // float4 index
            const int m  = (int)(i >> 8);
            const int c4 = (int)(i & 255);
            const int row = (m >> 6) * 128 + 3 + (m & 63);
            v[j] = __ldg((const float4*)(hidden + (size_t)row * 1024) + c4);
        }
        #pragma unroll
        for (int j = 0; j < 8; j++) {
            const size_t i = base + tid + j * 512;
            uint2 o;
            ((__half2*)&o)[0] = __floats2half2_rn(v[j].x, v[j].y);
            ((__half2*)&o)[1] = __floats2half2_rn(v[j].z, v[j].w);
            ((uint2*)g_Ah)[i] = o;
        }
    } else {
        const size_t base = (size_t)(blockIdx.x - 1024) * 4096;
        #pragma unroll
        for (int j = 0; j < 8; j++) {
            const size_t i = base + tid + j * 512;
            const int n  = (int)(i >> 8);
            const int c4 = (int)(i & 255);
            const float* src = (n < 256) ? (Wf + (size_t)n * 1024)
                                         : (Wt + (size_t)(n - 256) * 1024);
            v[j] = __ldg((const float4*)src + c4);
        }
        #pragma unroll
        for (int j = 0; j < 8; j++) {
            const size_t i = base + tid + j * 512;
            uint2 o;
            ((__half2*)&o)[0] = __floats2half2_rn(v[j].x, v[j].y);
            ((__half2*)&o)[1] = __floats2half2_rn(v[j].z, v[j].w);
            ((uint2*)g_Bh)[i] = o;
        }
    }
}

// ---------------------------------------------------------------------------
// fp16 tensor-core GEMM (R12 proven): grid (2,128): x=0 -> fp, 1 -> tp.
// 128(m) x 256(n) x 64(k) block tile, 512 threads = 16 warps (4m x 4n),
// warp tile 32x64. mma.sync.m16n8k16 f16->f32, 2-stage cp.async pipeline.
// smem/stage: A 128x72h (18432 B) + B 256x72h (36864 B) = 55296 B; 2 CTAs/SM.
// ---------------------------------------------------------------------------
#define KT 16                    // 1024/64 k-tiles
#define AST 72                   // halves per smem row (144 B)
#define ABUFH (128 * AST)
#define BBUFH (256 * AST)
#define GEMM_SMEM (2 * (ABUFH + BBUFH) * 2)   // 110592 B

__device__ __forceinline__ void mma_f16(float* c, const uint32_t* a, const uint32_t* b) {
    asm volatile(
        "mma.sync.aligned.m16n8k16.row.col.f32.f16.f16.f32 "
        "{%0,%1,%2,%3}, {%4,%5,%6,%7}, {%8,%9}, {%0,%1,%2,%3};"
        : "+f"(c[0]), "+f"(c[1]), "+f"(c[2]), "+f"(c[3])
        : "r"(a[0]), "r"(a[1]), "r"(a[2]), "r"(a[3]), "r"(b[0]), "r"(b[1]));
}

__global__ void __launch_bounds__(512) gemm_fpt_kernel(
    const float* __restrict__ bf, const float* __restrict__ bt)
{
    extern __shared__ __half hsm[];
    uint32_t sbase;
    asm("{ .reg .u64 t; cvta.to.shared.u64 t, %1; cvt.u32.u64 %0, t; }"
        : "=r"(sbase) : "l"(hsm));

    const int tid  = threadIdx.x;
    const int bn   = blockIdx.x;    // 0 = fp, 1 = tp
    const int bm   = blockIdx.y;
    const int warp = tid >> 5;
    const int lane = tid & 31;
    const int warp_m = warp >> 2;   // 0..3
    const int warp_n = warp & 3;    // 0..3
    const int lr = lane >> 2;       // 0..7
    const int lc = lane & 3;        // 0..3

    const __half* gAbase = g_Ah + (size_t)(bm * 128) * 1024;
    const __half* gBbase = g_Bh + (size_t)bn * 256 * 1024;

    float acc[2][8][4];
    #pragma unroll
    for (int i = 0; i < 2; i++)
        #pragma unroll
        for (int j = 0; j < 8; j++)
            #pragma unroll
            for (int k = 0; k < 4; k++) acc[i][j][k] = 0.f;

    auto load_tile = [&](int t, int stg) {
        const uint32_t aB = sbase + (uint32_t)stg * (ABUFH + BBUFH) * 2;
        const uint32_t bB = aB + ABUFH * 2;
        #pragma unroll
        for (int j = 0; j < 2; j++) {
            const int id  = tid + 512 * j;
            const int row = id >> 3;
            const int cc  = id & 7;
            asm volatile("cp.async.ca.shared.global [%0], [%1], 16;" ::
                "r"(aB + (uint32_t)(row * (AST * 2) + cc * 16)),
                "l"(gAbase + (size_t)row * 1024 + t * 64 + cc * 8));
        }
        #pragma unroll
        for (int j = 0; j < 4; j++) {
            const int id  = tid + 512 * j;
            const int row = id >> 3;
            const int cc  = id & 7;
            asm volatile("cp.async.ca.shared.global [%0], [%1], 16;" ::
                "r"(bB + (uint32_t)(row * (AST * 2) + cc * 16)),
                "l"(gBbase + (size_t)row * 1024 + t * 64 + cc * 8));
        }
        asm volatile("cp.async.commit_group;" ::: "memory");
    };

    load_tile(0, 0);

    int stg = 0;
    for (int t = 0; t < KT; t++) {
        asm volatile("cp.async.wait_group 0;" ::: "memory");
        __syncthreads();

        if (t + 1 < KT)
            load_tile(t + 1, stg ^ 1);

        const __half* Ab = hsm + (size_t)stg * (ABUFH + BBUFH);
        const __half* Bb = Ab + ABUFH;
        #pragma unroll
        for (int ks = 0; ks < 4; ks++) {
            uint32_t afr[2][4], bfr[8][2];
            #pragma unroll
            for (int mt = 0; mt < 2; mt++) {
                const __half* p = Ab + (warp_m * 32 + mt * 16 + lr) * AST + ks * 16 + 2 * lc;
                afr[mt][0] = *(const uint32_t*)(p);
                afr[mt][1] = *(const uint32_t*)(p + 8 * AST);
                afr[mt][2] = *(const uint32_t*)(p + 8);
                afr[mt][3] = *(const uint32_t*)(p + 8 * AST + 8);
            }
            #pragma unroll
            for (int nt = 0; nt < 8; nt++) {
                const __half* q = Bb + (warp_n * 64 + nt * 8 + lr) * AST + ks * 16 + 2 * lc;
                bfr[nt][0] = *(const uint32_t*)(q);
                bfr[nt][1] = *(const uint32_t*)(q + 8);
            }
            #pragma unroll
            for (int mt = 0; mt < 2; mt++)
                #pragma unroll
                for (int nt = 0; nt < 8; nt++)
                    mma_f16(acc[mt][nt], afr[mt], bfr[nt]);
        }
        stg ^= 1;
    }

    // epilogue: bias add in fp32, store fp16 half2
    const float* bia_base = bn ? bt : bf;
    __half* outp = bn ? g_tph : g_fph;
    #pragma unroll
    for (int mt = 0; mt < 2; mt++) {
        const int gm0 = bm * 128 + warp_m * 32 + mt * 16 + lr;
        #pragma unroll
        for (int nt = 0; nt < 8; nt++) {
            const int n_loc = warp_n * 64 + nt * 8 + (lc << 1);   // 0..255
            const float b0 = bia_base[n_loc], b1 = bia_base[n_loc + 1];
            *(__half2*)&outp[(size_t)gm0 * 256 + n_loc] =
                __floats2half2_rn(acc[mt][nt][0] + b0, acc[mt][nt][1] + b1);
            *(__half2*)&outp[(size_t)(gm0 + 8) * 256 + n_loc] =
                __floats2half2_rn(acc[mt][nt][2] + b0, acc[mt][nt][3] + b1);
        }
    }
}

// ---------------------------------------------------------------------------
// gp GEMM (fp32, tiny): 64 blocks x 4 batches.
// ---------------------------------------------------------------------------
__global__ void __launch_bounds__(256) gp_kernel(
    const float* __restrict__ hidden,
    const float* __restrict__ Wg, const float* __restrict__ bg)
{
    __shared__ float sh[4][1024];
    const int tid = threadIdx.x;
    const int b0  = blockIdx.x * 4;

    #pragma unroll
    for (int i = 0; i < 4; i++) {
        const int idx = tid + i * 256;
        const int row = idx >> 8;
        const int col = idx & 255;
        ((float4*)&sh[row][0])[col] =
            ((const float4*)(hidden + (size_t)(b0 + row) * 131072))[col];
    }
    __syncthreads();

    const int n = tid;
    const float4* w4 = (const float4*)(Wg + (size_t)n * 1024);
    float acc0 = 0.f, acc1 = 0.f, acc2 = 0.f, acc3 = 0.f;
    #pragma unroll 4
    for (int k4 = 0; k4 < 256; k4++) {
        const float4 w  = w4[k4];
        const float4 h0 = ((const float4*)&sh[0][0])[k4];
        const float4 h1 = ((const float4*)&sh[1][0])[k4];
        const float4 h2 = ((const float4*)&sh[2][0])[k4];
        const float4 h3 = ((const float4*)&sh[3][0])[k4];
        acc0 = fmaf(w.x, h0.x, acc0); acc0 = fmaf(w.y, h0.y, acc0);
        acc0 = fmaf(w.z, h0.z, acc0); acc0 = fmaf(w.w, h0.w, acc0);
        acc1 = fmaf(w.x, h1.x, acc1); acc1 = fmaf(w.y, h1.y, acc1);
        acc1 = fmaf(w.z, h1.z, acc1); acc1 = fmaf(w.w, h1.w, acc1);
        acc2 = fmaf(w.x, h2.x, acc2); acc2 = fmaf(w.y, h2.y, acc2);
        acc2 = fmaf(w.z, h2.z, acc2); acc2 = fmaf(w.w, h2.w, acc2);
        acc3 = fmaf(w.x, h3.x, acc3); acc3 = fmaf(w.y, h3.y, acc3);
        acc3 = fmaf(w.z, h3.z, acc3); acc3 = fmaf(w.w, h3.w, acc3);
    }
    const float bias = bg[n];
    g_gp[(size_t)(b0 + 0) * 256 + n] = acc0 + bias;
    g_gp[(size_t)(b0 + 1) * 256 + n] = acc1 + bias;
    g_gp[(size_t)(b0 + 2) * 256 + n] = acc2 + bias;
    g_gp[(size_t)(b0 + 3) * 256 + n] = acc3 + bias;
}

// ---------------------------------------------------------------------------
// Combine (R12 proven config): 256 blocks, 1024 threads.
// smem (fp16): fp 64x256 + tp 64x256 + gpp 5x256 = 68096 B, where
// gpp[p][d] = gp[b][d] + promo[p][d]. 2 v per warp iter; 6-shfl dual reduce.
// ---------------------------------------------------------------------------
__global__ void __launch_bounds__(1024) combine_kernel(
    const float* __restrict__ promo_tab, const float* __restrict__ Ws,
    const float* __restrict__ bs,
    const int* __restrict__ from_sqs, const int* __restrict__ to_sqs,
    const int* __restrict__ promo_types,
    float* __restrict__ out)
{
    extern __shared__ __half hsm2[];
    __half* fp_s  = hsm2;            // 16384 halves
    __half* tp_s  = hsm2 + 16384;    // 16384 halves
    __half* gpp_s = hsm2 + 32768;    // 1280 halves

    const int tid = threadIdx.x;
    const int b   = blockIdx.x;

    {
        const uint4* sf = (const uint4*)(g_fph + (size_t)b * 16384);
        const uint4* st = (const uint4*)(g_tph + (size_t)b * 16384);
        uint4* df = (uint4*)fp_s;
        uint4* dt = (uint4*)tp_s;
        df[tid] = sf[tid]; df[tid + 1024] = sf[tid + 1024];
        dt[tid] = st[tid]; dt[tid + 1024] = st[tid + 1024];
        if (tid < 640) {
            const int p  = tid >> 7;
            const int d2 = tid & 127;
            const float2 pv = ((const float2*)(promo_tab + p * 256))[d2];
            const float2 gv = ((const float2*)(g_gp + (size_t)b * 256))[d2];
            ((__half2*)gpp_s)[tid] = __floats2half2_rn(pv.x + gv.x, pv.y + gv.y);
        }
    }

    const int lane = tid & 31;
    const int warp = tid >> 5;

    const float4 wsa = *(const float4*)(Ws + lane * 8);
    const float4 wsb = *(const float4*)(Ws + lane * 8 + 4);
    const float wsr[8] = { wsa.x, wsa.y, wsa.z, wsa.w, wsb.x, wsb.y, wsb.z, wsb.w };
    const float bs0 = __ldg(bs);
    const __half2 hzero = __float2half2_rn(0.f);

    __syncthreads();

    for (int v0 = warp * 2; v0 < 1858; v0 += 64) {
        const int v1 = v0 + 1;
        const int f0 = __ldg(from_sqs + v0),    f1 = __ldg(from_sqs + v1);
        const int t0 = __ldg(to_sqs + v0),      t1 = __ldg(to_sqs + v1);
        const int p0 = __ldg(promo_types + v0), p1 = __ldg(promo_types + v1);

        const uint4 fh0 = *(const uint4*)(fp_s  + f0 * 256 + lane * 8);
        const uint4 th0 = *(const uint4*)(tp_s  + t0 * 256 + lane * 8);
        const uint4 gh0 = *(const uint4*)(gpp_s + p0 * 256 + lane * 8);
        const uint4 fh1 = *(const uint4*)(fp_s  + f1 * 256 + lane * 8);
        const uint4 th1 = *(const uint4*)(tp_s  + t1 * 256 + lane * 8);
        const uint4 gh1 = *(const uint4*)(gpp_s + p1 * 256 + lane * 8);

        const uint32_t* fw0 = (const uint32_t*)&fh0;
        const uint32_t* tw0 = (const uint32_t*)&th0;
        const uint32_t* gw0 = (const uint32_t*)&gh0;
        const uint32_t* fw1 = (const uint32_t*)&fh1;
        const uint32_t* tw1 = (const uint32_t*)&th1;
        const uint32_t* gw1 = (const uint32_t*)&gh1;

        float acc0 = 0.f, acc1 = 0.f;
        #pragma unroll
        for (int j = 0; j < 4; j++) {
            __half2 c0 = __hfma2(*(const __half2*)&fw0[j], *(const __half2*)&tw0[j],
                                 *(const __half2*)&gw0[j]);
            __half2 c1 = __hfma2(*(const __half2*)&fw1[j], *(const __half2*)&tw1[j],
                                 *(const __half2*)&gw1[j]);
            c0 = __hmax2(c0, hzero);
            c1 = __hmax2(c1, hzero);
            const float2 r0 = __half22float2(c0);
            const float2 r1 = __half22float2(c1);
            acc0 = fmaf(r0.x, wsr[2*j],     acc0);
            acc0 = fmaf(r0.y, wsr[2*j + 1], acc0);
            acc1 = fmaf(r1.x, wsr[2*j],     acc1);
            acc1 = fmaf(r1.y, wsr[2*j + 1], acc1);
        }

        // dual reduction: fold lane^16 for each chain, select halves, 4 levels
        const float a = acc0 + __shfl_xor_sync(0xffffffffu, acc0, 16);
        const float c = acc1 + __shfl_xor_sync(0xffffffffu, acc1, 16);
        float r = (lane & 16) ? c : a;
        r += __shfl_xor_sync(0xffffffffu, r, 8);
        r += __shfl_xor_sync(0xffffffffu, r, 4);
        r += __shfl_xor_sync(0xffffffffu, r, 2);
        r += __shfl_xor_sync(0xffffffffu, r, 1);
        if (lane == 0)  out[(size_t)b * 1858 + v0] = r + bs0;
        if (lane == 16) out[(size_t)b * 1858 + v1] = r + bs0;
    }
}

// ---------------------------------------------------------------------------
extern "C" void kernel_launch(void* const* d_in, const int* in_sizes, int n_in,
                              void* d_out, int out_size)
{
    (void)in_sizes; (void)n_in; (void)out_size;

    const float* hidden      = (const float*)d_in[0];
    const float* Wf          = (const float*)d_in[1];
    const float* bf          = (const float*)d_in[2];
    const float* Wt          = (const float*)d_in[3];
    const float* bt          = (const float*)d_in[4];
    const float* Wg          = (const float*)d_in[5];
    const float* bg          = (const float*)d_in[6];
    const float* promo_tab   = (const float*)d_in[7];
    const float* Ws          = (const float*)d_in[8];
    const float* bs          = (const float*)d_in[9];
    const int*   from_sqs    = (const int*)d_in[10];
    const int*   to_sqs      = (const int*)d_in[11];
    const int*   promo_types = (const int*)d_in[12];
    float*       out         = (float*)d_out;

    // 1) gather + fp16 convert pre-pass (MLP-8)
    conv_kernel<<<1056, 512>>>(hidden, Wf, Wt);

    // 2) fp16 tensor-core fp/tp GEMM (128x256x64, 16 warps, 2-stage, 2 CTA/SM)
    cudaFuncSetAttribute(gemm_fpt_kernel,
                         cudaFuncAttributeMaxDynamicSharedMemorySize, GEMM_SMEM);
    gemm_fpt_kernel<<<dim3(2, 128), 512, GEMM_SMEM>>>(bf, bt);

    // 3) gp
    gp_kernel<<<64, 256>>>(hidden, Wg, bg);

    // 4) combine (proven config)
    const int comb_smem = (16384 + 16384 + 1280) * 2;   // 68096 B
    cudaFuncSetAttribute(combine_kernel,
                         cudaFuncAttributeMaxDynamicSharedMemorySize, comb_smem);
    combine_kernel<<<256, 1024, comb_smem>>>(promo_tab, Ws, bs,
                                             from_sqs, to_sqs, promo_types, out);
}

// round 16
// speedup vs baseline: 1.2817x; 1.0528x over previous
#include <cuda_runtime.h>
#include <cuda_fp16.h>
#include <cstdint>

// ---------------------------------------------------------------------------
// SpatialPolicyHead: B=256, S=128 (rows 3..66 + row 0), H=1024, D=256, V=1858
//   fp = sq_hidden @ Wf^T + bf          (B*64, 256)
//   tp = sq_hidden @ Wt^T + bt          (B*64, 256)
//   gp = hidden[:,0,:] @ Wg^T + bg      (B, 256)
//   out[b,v] = sum_d relu(fp[b,f(v),d]*tp[b,t(v),d] + gp[b,d] + promo[p(v),d])*Ws[d] + bs
//
// R16: A gather + fp16 conversion fused INTO the GEMM (LDG fp32 -> CVT ->
// STS fp16, latency hidden behind tile compute). conv reduced to B only.
// GEMM shape = R12 proven (128x256x64, 16 warps, 2-stage fp16 smem).
// ---------------------------------------------------------------------------

// scratch (static device globals -- allocation-free)
__device__ __half g_Bh[512 * 1024];     // Wf (0..255) ++ Wt (256..511), fp16
__device__ __half g_fph[16384 * 256];   // fp results, fp16
__device__ __half g_tph[16384 * 256];   // tp results, fp16
__device__ float  g_gp [256 * 256];     // [B][256] fp32

// ---------------------------------------------------------------------------
// B conversion only: 128 blocks x 256 threads (512x1024 fp32 -> fp16).
// ---------------------------------------------------------------------------
__global__ void __launch_bounds__(256) convB_kernel(
    const float* __restrict__ Wf, const float* __restrict__ Wt)
{
    const int tid = threadIdx.x;
    const size_t base = (size_t)blockIdx.x * 1024;
    #pragma unroll
    for (int j = 0; j < 4; j++) {
        const size_t i = base + tid + j * 256;   // float4 index
        const int n  = (int)(i >> 8);
        const int c4 = (int)(i & 255);
        const float* src = (n < 256) ? (Wf + (size_t)n * 1024)
                                     : (Wt + (size_t)(n - 256) * 1024);
        const float4 v = __ldg((const float4*)src + c4);
        uint2 o;
        ((__half2*)&o)[0] = __floats2half2_rn(v.x, v.y);
        ((__half2*)&o)[1] = __floats2half2_rn(v.z, v.w);
        ((uint2*)g_Bh)[i] = o;
    }
}

// ---------------------------------------------------------------------------
// fp16 tensor-core GEMM with fused A gather/convert.
// grid (2,128): x=0 -> fp, 1 -> tp. 128(m) x 256(n) x 64(k) block tile,
// 512 threads = 16 warps (4m x 4n), warp tile 32x64, mma.sync.m16n8k16.
// A: LDG.128 fp32 from hidden (gathered rows) -> CVT -> STS fp16 into next
// stage, issued around the compute phase. B: cp.async double buffer.
// smem/stage: A 128x72h (18432 B) + B 256x72h (36864 B) = 55296 B.
// ---------------------------------------------------------------------------
#define KT 16                    // 1024/64 k-tiles
#define AST 72                   // halves per smem row (144 B)
#define ABUFH (128 * AST)
#define BBUFH (256 * AST)
#define STGH  (ABUFH + BBUFH)    // halves per stage
#define GEMM_SMEM (2 * STGH * 2) // 110592 B

__device__ __forceinline__ void mma_f16(float* c, const uint32_t* a, const uint32_t* b) {
    asm volatile(
        "mma.sync.aligned.m16n8k16.row.col.f32.f16.f16.f32 "
        "{%0,%1,%2,%3}, {%4,%5,%6,%7}, {%8,%9}, {%0,%1,%2,%3};"
        : "+f"(c[0]), "+f"(c[1]), "+f"(c[2]), "+f"(c[3])
        : "r"(a[0]), "r"(a[1]), "r"(a[2]), "r"(a[3]), "r"(b[0]), "r"(b[1]));
}

__global__ void __launch_bounds__(512) gemm_fpt_kernel(
    const float* __restrict__ hidden,
    const float* __restrict__ bf, const float* __restrict__ bt)
{
    extern __shared__ __half hsm[];
    uint32_t sbase;
    asm("{ .reg .u64 t; cvta.to.shared.u64 t, %1; cvt.u32.u64 %0, t; }"
        : "=r"(sbase) : "l"(hsm));

    const int tid  = threadIdx.x;
    const int bn   = blockIdx.x;    // 0 = fp, 1 = tp
    const int bm   = blockIdx.y;
    const int warp = tid >> 5;
    const int lane = tid & 31;
    const int warp_m = warp >> 2;   // 0..3
    const int warp_n = warp & 3;    // 0..3
    const int lr = lane >> 2;       // 0..7
    const int lc = lane & 3;        // 0..3

    // A direct-gather mapping: 128 rows x 16 float4-chunks = 2048 -> 4/thread
    // chunk id = tid + 512*j: row = id>>4, cc = id&15
    int  a_goff[4];   // float offset into hidden for t=0
    int  a_soff[4];   // half offset into A stage buffer
    #pragma unroll
    for (int j = 0; j < 4; j++) {
        const int id  = tid + 512 * j;
        const int row = id >> 4;
        const int cc  = id & 15;
        const int hrow = (bm * 2 + (row >> 6)) * 128 + 3 + (row & 63);
        a_goff[j] = hrow * 1024 + cc * 4;
        a_soff[j] = row * AST + cc * 4;
    }

    const __half* gBbase = g_Bh + (size_t)bn * 256 * 1024;

    float acc[2][8][4];
    #pragma unroll
    for (int i = 0; i < 2; i++)
        #pragma unroll
        for (int j = 0; j < 8; j++)
            #pragma unroll
            for (int k = 0; k < 4; k++) acc[i][j][k] = 0.f;

    float4 va[4];

    auto ldgA = [&](int t) {
        #pragma unroll
        for (int j = 0; j < 4; j++)
            va[j] = __ldg((const float4*)(hidden + a_goff[j] + t * 64));
    };
    auto stsA = [&](int stg) {
        __half* ab = hsm + stg * STGH;
        #pragma unroll
        for (int j = 0; j < 4; j++) {
            uint2 o;
            ((__half2*)&o)[0] = __floats2half2_rn(va[j].x, va[j].y);
            ((__half2*)&o)[1] = __floats2half2_rn(va[j].z, va[j].w);
            *(uint2*)(ab + a_soff[j]) = o;
        }
    };
    auto cpB = [&](int t, int stg) {
        const uint32_t bB = sbase + (uint32_t)(stg * STGH + ABUFH) * 2;
        #pragma unroll
        for (int j = 0; j < 4; j++) {
            const int id  = tid + 512 * j;
            const int row = id >> 3;
            const int cc  = id & 7;
            asm volatile("cp.async.ca.shared.global [%0], [%1], 16;" ::
                "r"(bB + (uint32_t)(row * (AST * 2) + cc * 16)),
                "l"(gBbase + (size_t)row * 1024 + t * 64 + cc * 8));
        }
        asm volatile("cp.async.commit_group;" ::: "memory");
    };

    // prologue: A(0) -> regs -> buf0 ; B(0) -> buf0
    ldgA(0);
    stsA(0);
    cpB(0, 0);

    for (int t = 0; t < KT; t++) {
        const int stg = t & 1;
        asm volatile("cp.async.wait_group 0;" ::: "memory");
        __syncthreads();

        if (t + 1 < KT) {
            cpB(t + 1, stg ^ 1);
            ldgA(t + 1);           // latency hidden behind compute below
        }

        const __half* Ab = hsm + stg * STGH;
        const __half* Bb = Ab + ABUFH;
        #pragma unroll
        for (int ks = 0; ks < 4; ks++) {
            uint32_t afr[2][4], bfr[8][2];
            #pragma unroll
            for (int mt = 0; mt < 2; mt++) {
                const __half* p = Ab + (warp_m * 32 + mt * 16 + lr) * AST + ks * 16 + 2 * lc;
                afr[mt][0] = *(const uint32_t*)(p);
                afr[mt][1] = *(const uint32_t*)(p + 8 * AST);
                afr[mt][2] = *(const uint32_t*)(p + 8);
                afr[mt][3] = *(const uint32_t*)(p + 8 * AST + 8);
            }
            #pragma unroll
            for (int nt = 0; nt < 8; nt++) {
                const __half* q = Bb + (warp_n * 64 + nt * 8 + lr) * AST + ks * 16 + 2 * lc;
                bfr[nt][0] = *(const uint32_t*)(q);
                bfr[nt][1] = *(const uint32_t*)(q + 8);
            }
            #pragma unroll
            for (int mt = 0; mt < 2; mt++)
                #pragma unroll
                for (int nt = 0; nt < 8; nt++)
                    mma_f16(acc[mt][nt], afr[mt], bfr[nt]);
        }

        if (t + 1 < KT)
            stsA(stg ^ 1);         // write NEXT stage; current readers use stg
    }

    // epilogue: bias add in fp32, store fp16 half2
    const float* bia_base = bn ? bt : bf;
    __half* outp = bn ? g_tph : g_fph;
    #pragma unroll
    for (int mt = 0; mt < 2; mt++) {
        const int gm0 = bm * 128 + warp_m * 32 + mt * 16 + lr;
        #pragma unroll
        for (int nt = 0; nt < 8; nt++) {
            const int n_loc = warp_n * 64 + nt * 8 + (lc << 1);   // 0..255
            const float b0 = bia_base[n_loc], b1 = bia_base[n_loc + 1];
            *(__half2*)&outp[(size_t)gm0 * 256 + n_loc] =
                __floats2half2_rn(acc[mt][nt][0] + b0, acc[mt][nt][1] + b1);
            *(__half2*)&outp[(size_t)(gm0 + 8) * 256 + n_loc] =
                __floats2half2_rn(acc[mt][nt][2] + b0, acc[mt][nt][3] + b1);
        }
    }
}

// ---------------------------------------------------------------------------
// gp GEMM (fp32, tiny): 64 blocks x 4 batches.
// ---------------------------------------------------------------------------
__global__ void __launch_bounds__(256) gp_kernel(
    const float* __restrict__ hidden,
    const float* __restrict__ Wg, const float* __restrict__ bg)
{
    __shared__ float sh[4][1024];
    const int tid = threadIdx.x;
    const int b0  = blockIdx.x * 4;

    #pragma unroll
    for (int i = 0; i < 4; i++) {
        const int idx = tid + i * 256;
        const int row = idx >> 8;
        const int col = idx & 255;
        ((float4*)&sh[row][0])[col] =
            ((const float4*)(hidden + (size_t)(b0 + row) * 131072))[col];
    }
    __syncthreads();

    const int n = tid;
    const float4* w4 = (const float4*)(Wg + (size_t)n * 1024);
    float acc0 = 0.f, acc1 = 0.f, acc2 = 0.f, acc3 = 0.f;
    #pragma unroll 4
    for (int k4 = 0; k4 < 256; k4++) {
        const float4 w  = w4[k4];
        const float4 h0 = ((const float4*)&sh[0][0])[k4];
        const float4 h1 = ((const float4*)&sh[1][0])[k4];
        const float4 h2 = ((const float4*)&sh[2][0])[k4];
        const float4 h3 = ((const float4*)&sh[3][0])[k4];
        acc0 = fmaf(w.x, h0.x, acc0); acc0 = fmaf(w.y, h0.y, acc0);
        acc0 = fmaf(w.z, h0.z, acc0); acc0 = fmaf(w.w, h0.w, acc0);
        acc1 = fmaf(w.x, h1.x, acc1); acc1 = fmaf(w.y, h1.y, acc1);
        acc1 = fmaf(w.z, h1.z, acc1); acc1 = fmaf(w.w, h1.w, acc1);
        acc2 = fmaf(w.x, h2.x, acc2); acc2 = fmaf(w.y, h2.y, acc2);
        acc2 = fmaf(w.z, h2.z, acc2); acc2 = fmaf(w.w, h2.w, acc2);
        acc3 = fmaf(w.x, h3.x, acc3); acc3 = fmaf(w.y, h3.y, acc3);
        acc3 = fmaf(w.z, h3.z, acc3); acc3 = fmaf(w.w, h3.w, acc3);
    }
    const float bias = bg[n];
    g_gp[(size_t)(b0 + 0) * 256 + n] = acc0 + bias;
    g_gp[(size_t)(b0 + 1) * 256 + n] = acc1 + bias;
    g_gp[(size_t)(b0 + 2) * 256 + n] = acc2 + bias;
    g_gp[(size_t)(b0 + 3) * 256 + n] = acc3 + bias;
}

// ---------------------------------------------------------------------------
// Combine (R12 proven config): 256 blocks, 1024 threads.
// smem (fp16): fp 64x256 + tp 64x256 + gpp 5x256 = 68096 B, where
// gpp[p][d] = gp[b][d] + promo[p][d]. 2 v per warp iter; 6-shfl dual reduce.
// ---------------------------------------------------------------------------
__global__ void __launch_bounds__(1024) combine_kernel(
    const float* __restrict__ promo_tab, const float* __restrict__ Ws,
    const float* __restrict__ bs,
    const int* __restrict__ from_sqs, const int* __restrict__ to_sqs,
    const int* __restrict__ promo_types,
    float* __restrict__ out)
{
    extern __shared__ __half hsm2[];
    __half* fp_s  = hsm2;            // 16384 halves
    __half* tp_s  = hsm2 + 16384;    // 16384 halves
    __half* gpp_s = hsm2 + 32768;    // 1280 halves

    const int tid = threadIdx.x;
    const int b   = blockIdx.x;

    {
        const uint4* sf = (const uint4*)(g_fph + (size_t)b * 16384);
        const uint4* st = (const uint4*)(g_tph + (size_t)b * 16384);
        uint4* df = (uint4*)fp_s;
        uint4* dt = (uint4*)tp_s;
        df[tid] = sf[tid]; df[tid + 1024] = sf[tid + 1024];
        dt[tid] = st[tid]; dt[tid + 1024] = st[tid + 1024];
        if (tid < 640) {
            const int p  = tid >> 7;
            const int d2 = tid & 127;
            const float2 pv = ((const float2*)(promo_tab + p * 256))[d2];
            const float2 gv = ((const float2*)(g_gp + (size_t)b * 256))[d2];
            ((__half2*)gpp_s)[tid] = __floats2half2_rn(pv.x + gv.x, pv.y + gv.y);
        }
    }

    const int lane = tid & 31;
    const int warp = tid >> 5;

    const float4 wsa = *(const float4*)(Ws + lane * 8);
    const float4 wsb = *(const float4*)(Ws + lane * 8 + 4);
    const float wsr[8] = { wsa.x, wsa.y, wsa.z, wsa.w, wsb.x, wsb.y, wsb.z, wsb.w };
    const float bs0 = __ldg(bs);
    const __half2 hzero = __float2half2_rn(0.f);

    __syncthreads();

    for (int v0 = warp * 2; v0 < 1858; v0 += 64) {
        const int v1 = v0 + 1;
        const int f0 = __ldg(from_sqs + v0),    f1 = __ldg(from_sqs + v1);
        const int t0 = __ldg(to_sqs + v0),      t1 = __ldg(to_sqs + v1);
        const int p0 = __ldg(promo_types + v0), p1 = __ldg(promo_types + v1);

        const uint4 fh0 = *(const uint4*)(fp_s  + f0 * 256 + lane * 8);
        const uint4 th0 = *(const uint4*)(tp_s  + t0 * 256 + lane * 8);
        const uint4 gh0 = *(const uint4*)(gpp_s + p0 * 256 + lane * 8);
        const uint4 fh1 = *(const uint4*)(fp_s  + f1 * 256 + lane * 8);
        const uint4 th1 = *(const uint4*)(tp_s  + t1 * 256 + lane * 8);
        const uint4 gh1 = *(const uint4*)(gpp_s + p1 * 256 + lane * 8);

        const uint32_t* fw0 = (const uint32_t*)&fh0;
        const uint32_t* tw0 = (const uint32_t*)&th0;
        const uint32_t* gw0 = (const uint32_t*)&gh0;
        const uint32_t* fw1 = (const uint32_t*)&fh1;
        const uint32_t* tw1 = (const uint32_t*)&th1;
        const uint32_t* gw1 = (const uint32_t*)&gh1;

        float acc0 = 0.f, acc1 = 0.f;
        #pragma unroll
        for (int j = 0; j < 4; j++) {
            __half2 c0 = __hfma2(*(const __half2*)&fw0[j], *(const __half2*)&tw0[j],
                                 *(const __half2*)&gw0[j]);
            __half2 c1 = __hfma2(*(const __half2*)&fw1[j], *(const __half2*)&tw1[j],
                                 *(const __half2*)&gw1[j]);
            c0 = __hmax2(c0, hzero);
            c1 = __hmax2(c1, hzero);
            const float2 r0 = __half22float2(c0);
            const float2 r1 = __half22float2(c1);
            acc0 = fmaf(r0.x, wsr[2*j],     acc0);
            acc0 = fmaf(r0.y, wsr[2*j + 1], acc0);
            acc1 = fmaf(r1.x, wsr[2*j],     acc1);
            acc1 = fmaf(r1.y, wsr[2*j + 1], acc1);
        }

        // dual reduction: fold lane^16 for each chain, select halves, 4 levels
        const float a = acc0 + __shfl_xor_sync(0xffffffffu, acc0, 16);
        const float c = acc1 + __shfl_xor_sync(0xffffffffu, acc1, 16);
        float r = (lane & 16) ? c : a;
        r += __shfl_xor_sync(0xffffffffu, r, 8);
        r += __shfl_xor_sync(0xffffffffu, r, 4);
        r += __shfl_xor_sync(0xffffffffu, r, 2);
        r += __shfl_xor_sync(0xffffffffu, r, 1);
        if (lane == 0)  out[(size_t)b * 1858 + v0] = r + bs0;
        if (lane == 16) out[(size_t)b * 1858 + v1] = r + bs0;
    }
}

// ---------------------------------------------------------------------------
extern "C" void kernel_launch(void* const* d_in, const int* in_sizes, int n_in,
                              void* d_out, int out_size)
{
    (void)in_sizes; (void)n_in; (void)out_size;

    const float* hidden      = (const float*)d_in[0];
    const float* Wf          = (const float*)d_in[1];
    const float* bf          = (const float*)d_in[2];
    const float* Wt          = (const float*)d_in[3];
    const float* bt          = (const float*)d_in[4];
    const float* Wg          = (const float*)d_in[5];
    const float* bg          = (const float*)d_in[6];
    const float* promo_tab   = (const float*)d_in[7];
    const float* Ws          = (const float*)d_in[8];
    const float* bs          = (const float*)d_in[9];
    const int*   from_sqs    = (const int*)d_in[10];
    const int*   to_sqs      = (const int*)d_in[11];
    const int*   promo_types = (const int*)d_in[12];
    float*       out         = (float*)d_out;

    // 1) B fp16 conversion (tiny)
    convB_kernel<<<128, 256>>>(Wf, Wt);

    // 2) fp16 tensor-core GEMM with fused A gather/convert
    cudaFuncSetAttribute(gemm_fpt_kernel,
                         cudaFuncAttributeMaxDynamicSharedMemorySize, GEMM_SMEM);
    gemm_fpt_kernel<<<dim3(2, 128), 512, GEMM_SMEM>>>(hidden, bf, bt);

    // 3) gp
    gp_kernel<<<64, 256>>>(hidden, Wg, bg);

    // 4) combine (proven config)
    const int comb_smem = (16384 + 16384 + 1280) * 2;   // 68096 B
    cudaFuncSetAttribute(combine_kernel,
                         cudaFuncAttributeMaxDynamicSharedMemorySize, comb_smem);
    combine_kernel<<<256, 1024, comb_smem>>>(promo_tab, Ws, bs,
                                             from_sqs, to_sqs, promo_types, out);
}